// round 1
// baseline (speedup 1.0000x reference)
#include <cuda_runtime.h>

#define NN 50000
#define NE 800000
#define CH 64
#define ETOT (NE + NN)

// ---------------- scratch (device globals; no allocation allowed) ----------
__device__ float g_l[NN * CH];
__device__ float g_r[NN * CH];
__device__ float g_res[NN * CH];
__device__ float g_dl[NN * CH];
__device__ float g_dr[NN * CH];
__device__ float g_ftr[NN * CH];
__device__ float g_ftl[NN * CH];

__device__ __forceinline__ float expsig(float x) {
    // exp(sigmoid(x)); sigmoid output in (0,1) so exp is in (1,e): always safe
    return __expf(__frcp_rn(1.f + __expf(-x)));
}

// ---------------- zero the accumulators ------------------------------------
__global__ void zero_kernel() {
    int i = blockIdx.x * blockDim.x + threadIdx.x;
    if (i < NN * CH / 4) {
        float4 z = make_float4(0.f, 0.f, 0.f, 0.f);
        reinterpret_cast<float4*>(g_dl)[i]  = z;
        reinterpret_cast<float4*>(g_dr)[i]  = z;
        reinterpret_cast<float4*>(g_ftr)[i] = z;
        reinterpret_cast<float4*>(g_ftl)[i] = z;
    }
}

// ---------------- node pass: minmax norm + three 64x64 GEMVs ---------------
// 256 threads/block, 4 nodes per block (64 threads per node, one per out feat)
__global__ void node_proj_kernel(const float* __restrict__ ndata,
                                 const float* __restrict__ W1,
                                 const float* __restrict__ b1,
                                 const float* __restrict__ W2,
                                 const float* __restrict__ b2,
                                 const float* __restrict__ Wres,
                                 const float* __restrict__ bres) {
    __shared__ float rmin[4][64];
    __shared__ float rmax[4][64];
    __shared__ float sx[4][64];

    int g = threadIdx.x >> 6;        // node group within block: 0..3
    int f = threadIdx.x & 63;        // feature: 0..63
    int n = blockIdx.x * 4 + g;

    float v = (n < NN) ? ndata[n * CH + f] : 0.f;
    rmin[g][f] = v;
    rmax[g][f] = v;
    __syncthreads();
    #pragma unroll
    for (int off = 32; off > 0; off >>= 1) {
        if (f < off) {
            rmin[g][f] = fminf(rmin[g][f], rmin[g][f + off]);
            rmax[g][f] = fmaxf(rmax[g][f], rmax[g][f + off]);
        }
        __syncthreads();
    }
    float mn = rmin[g][0];
    float mx = rmax[g][0];
    float x = (v - mn) / (mx - mn + 1e-5f);
    sx[g][f] = x;
    __syncthreads();

    if (n < NN) {
        float a1 = __ldg(&b1[f]);
        float a2 = __ldg(&b2[f]);
        float ar = __ldg(&bres[f]);
        #pragma unroll
        for (int k = 0; k < CH; k++) {
            float xv = sx[g][k];
            a1 = fmaf(xv, __ldg(&W1[k * CH + f]), a1);
            a2 = fmaf(xv, __ldg(&W2[k * CH + f]), a2);
            ar = fmaf(xv, __ldg(&Wres[k * CH + f]), ar);
        }
        g_l[n * CH + f]   = a1;
        g_r[n * CH + f]   = a2;
        g_res[n * CH + f] = ar;
    }
}

// ---------------- edge pass 1: softmax denominators (both l and r) ---------
// one warp per edge, float2 per lane (64 features)
__global__ void edge_denom_kernel(const int* __restrict__ src,
                                  const int* __restrict__ dst) {
    int e = blockIdx.x * (blockDim.x >> 5) + (threadIdx.x >> 5);
    if (e >= ETOT) return;
    int lane = threadIdx.x & 31;
    int s, d;
    if (e < NE) { s = src[e]; d = dst[e]; }
    else        { s = e - NE; d = s; }

    float2 ls = reinterpret_cast<const float2*>(g_l + s * CH)[lane];
    float2 ld = reinterpret_cast<const float2*>(g_l + d * CH)[lane];
    float2 rs = reinterpret_cast<const float2*>(g_r + s * CH)[lane];
    float2 rd = reinterpret_cast<const float2*>(g_r + d * CH)[lane];

    float el0 = expsig(ls.x + ld.x);
    float el1 = expsig(ls.y + ld.y);
    float er0 = expsig(rs.x + rd.x);
    float er1 = expsig(rs.y + rd.y);

    atomicAdd(&g_dl[d * CH + 2 * lane],     el0);
    atomicAdd(&g_dl[d * CH + 2 * lane + 1], el1);
    atomicAdd(&g_dr[d * CH + 2 * lane],     er0);
    atomicAdd(&g_dr[d * CH + 2 * lane + 1], er1);
}

// ---------------- edge pass 2: ft_r[d] += r[s] * softmax_l(e) --------------
__global__ void edge_ftr_kernel(const int* __restrict__ src,
                                const int* __restrict__ dst) {
    int e = blockIdx.x * (blockDim.x >> 5) + (threadIdx.x >> 5);
    if (e >= ETOT) return;
    int lane = threadIdx.x & 31;
    int s, d;
    if (e < NE) { s = src[e]; d = dst[e]; }
    else        { s = e - NE; d = s; }

    float2 ls = reinterpret_cast<const float2*>(g_l + s * CH)[lane];
    float2 ld = reinterpret_cast<const float2*>(g_l + d * CH)[lane];
    float2 dl = reinterpret_cast<const float2*>(g_dl + d * CH)[lane];
    float2 rs = reinterpret_cast<const float2*>(g_r + s * CH)[lane];

    float w0 = expsig(ls.x + ld.x) / dl.x;
    float w1 = expsig(ls.y + ld.y) / dl.y;

    atomicAdd(&g_ftr[d * CH + 2 * lane],     rs.x * w0);
    atomicAdd(&g_ftr[d * CH + 2 * lane + 1], rs.y * w1);
}

// ---------------- edge pass 3: ft_l[d] += ft_r[s] * softmax_r(e) -----------
__global__ void edge_ftl_kernel(const int* __restrict__ src,
                                const int* __restrict__ dst) {
    int e = blockIdx.x * (blockDim.x >> 5) + (threadIdx.x >> 5);
    if (e >= ETOT) return;
    int lane = threadIdx.x & 31;
    int s, d;
    if (e < NE) { s = src[e]; d = dst[e]; }
    else        { s = e - NE; d = s; }

    float2 rs  = reinterpret_cast<const float2*>(g_r + s * CH)[lane];
    float2 rd  = reinterpret_cast<const float2*>(g_r + d * CH)[lane];
    float2 dr  = reinterpret_cast<const float2*>(g_dr + d * CH)[lane];
    float2 frs = reinterpret_cast<const float2*>(g_ftr + s * CH)[lane];

    float w0 = expsig(rs.x + rd.x) / dr.x;
    float w1 = expsig(rs.y + rd.y) / dr.y;

    atomicAdd(&g_ftl[d * CH + 2 * lane],     frs.x * w0);
    atomicAdd(&g_ftl[d * CH + 2 * lane + 1], frs.y * w1);
}

// ---------------- final: out = m0 * ft_l + res ------------------------------
__global__ void final_kernel(const float* __restrict__ m, float* __restrict__ out) {
    int i = blockIdx.x * blockDim.x + threadIdx.x;
    if (i < NN * CH) {
        out[i] = __ldg(&m[i & 63]) * g_ftl[i] + g_res[i];
    }
}

extern "C" void kernel_launch(void* const* d_in, const int* in_sizes, int n_in,
                              void* d_out, int out_size) {
    const float* ndata = (const float*)d_in[0];
    const int*   src   = (const int*)d_in[1];
    const int*   dst   = (const int*)d_in[2];
    const float* W1    = (const float*)d_in[3];
    const float* b1    = (const float*)d_in[4];
    const float* W2    = (const float*)d_in[5];
    const float* b2    = (const float*)d_in[6];
    const float* Wres  = (const float*)d_in[7];
    const float* bres  = (const float*)d_in[8];
    const float* m     = (const float*)d_in[9];
    float* out = (float*)d_out;

    // zero accumulators
    {
        int total = NN * CH / 4;
        zero_kernel<<<(total + 255) / 256, 256>>>();
    }
    // node projections
    node_proj_kernel<<<(NN + 3) / 4, 256>>>(ndata, W1, b1, W2, b2, Wres, bres);

    // edge passes: one warp per edge, 8 warps per block
    int eblocks = (ETOT + 7) / 8;
    edge_denom_kernel<<<eblocks, 256>>>(src, dst);
    edge_ftr_kernel<<<eblocks, 256>>>(src, dst);
    edge_ftl_kernel<<<eblocks, 256>>>(src, dst);

    // epilogue
    final_kernel<<<(NN * CH + 255) / 256, 256>>>(m, out);
}

// round 2
// speedup vs baseline: 1.3711x; 1.3711x over previous
#include <cuda_runtime.h>

#define NN 50000
#define NE 800000
#define CH 64
#define ETOT (NE + NN)

// ---------------- scratch (device globals; no allocation allowed) ----------
__device__ float g_l[NN * CH];
__device__ float g_r[NN * CH];
__device__ float g_res[NN * CH];
__device__ float g_dl[NN * CH];
__device__ float g_dr[NN * CH];
__device__ float g_ftr[NN * CH];
__device__ float g_ftl[NN * CH];

__device__ __forceinline__ float expsig(float x) {
    // exp(sigmoid(x)); sigmoid in (0,1) so exp in (1,e): overflow-safe,
    // and exp(v)/sum(exp(v)) == exp(v-mx)/sum(exp(v-mx)) exactly in math.
    return __expf(__frcp_rn(1.f + __expf(-x)));
}

__device__ __forceinline__ void red_add_v4(float* p, float4 v) {
    asm volatile("red.global.v4.f32.add [%0], {%1,%2,%3,%4};"
                 :: "l"(p), "f"(v.x), "f"(v.y), "f"(v.z), "f"(v.w)
                 : "memory");
}

// ---------------- zero the accumulators ------------------------------------
__global__ void zero_kernel() {
    int i = blockIdx.x * blockDim.x + threadIdx.x;
    if (i < NN * CH / 4) {
        float4 z = make_float4(0.f, 0.f, 0.f, 0.f);
        reinterpret_cast<float4*>(g_dl)[i]  = z;
        reinterpret_cast<float4*>(g_dr)[i]  = z;
        reinterpret_cast<float4*>(g_ftr)[i] = z;
        reinterpret_cast<float4*>(g_ftl)[i] = z;
    }
}

// ---------------- node pass: minmax norm + three 64x64 GEMVs ---------------
__global__ void node_proj_kernel(const float* __restrict__ ndata,
                                 const float* __restrict__ W1,
                                 const float* __restrict__ b1,
                                 const float* __restrict__ W2,
                                 const float* __restrict__ b2,
                                 const float* __restrict__ Wres,
                                 const float* __restrict__ bres) {
    __shared__ float rmin[4][64];
    __shared__ float rmax[4][64];
    __shared__ float sx[4][64];

    int g = threadIdx.x >> 6;
    int f = threadIdx.x & 63;
    int n = blockIdx.x * 4 + g;

    float v = (n < NN) ? ndata[n * CH + f] : 0.f;
    rmin[g][f] = v;
    rmax[g][f] = v;
    __syncthreads();
    #pragma unroll
    for (int off = 32; off > 0; off >>= 1) {
        if (f < off) {
            rmin[g][f] = fminf(rmin[g][f], rmin[g][f + off]);
            rmax[g][f] = fmaxf(rmax[g][f], rmax[g][f + off]);
        }
        __syncthreads();
    }
    float mn = rmin[g][0];
    float mx = rmax[g][0];
    float x = (v - mn) / (mx - mn + 1e-5f);
    sx[g][f] = x;
    __syncthreads();

    if (n < NN) {
        float a1 = __ldg(&b1[f]);
        float a2 = __ldg(&b2[f]);
        float ar = __ldg(&bres[f]);
        #pragma unroll
        for (int k = 0; k < CH; k++) {
            float xv = sx[g][k];
            a1 = fmaf(xv, __ldg(&W1[k * CH + f]), a1);
            a2 = fmaf(xv, __ldg(&W2[k * CH + f]), a2);
            ar = fmaf(xv, __ldg(&Wres[k * CH + f]), ar);
        }
        g_l[n * CH + f]   = a1;
        g_r[n * CH + f]   = a2;
        g_res[n * CH + f] = ar;
    }
}

// ---------------- edge pass 1: unnormalized softmax denominators -----------
// 2 edges per warp; 16 lanes per edge; float4 per lane.
__global__ void __launch_bounds__(256) edge_denom_kernel(const int* __restrict__ src,
                                                         const int* __restrict__ dst) {
    int warp = blockIdx.x * (blockDim.x >> 5) + (threadIdx.x >> 5);
    int e = warp * 2 + ((threadIdx.x >> 4) & 1);
    if (e >= ETOT) return;
    int q = threadIdx.x & 15;
    int s, d;
    if (e < NE) { s = src[e]; d = dst[e]; }
    else        { s = e - NE; d = s; }

    float4 ls = reinterpret_cast<const float4*>(g_l + s * CH)[q];
    float4 ld = reinterpret_cast<const float4*>(g_l + d * CH)[q];
    float4 rs = reinterpret_cast<const float4*>(g_r + s * CH)[q];
    float4 rd = reinterpret_cast<const float4*>(g_r + d * CH)[q];

    float4 el = make_float4(expsig(ls.x + ld.x), expsig(ls.y + ld.y),
                            expsig(ls.z + ld.z), expsig(ls.w + ld.w));
    float4 er = make_float4(expsig(rs.x + rd.x), expsig(rs.y + rd.y),
                            expsig(rs.z + rd.z), expsig(rs.w + rd.w));

    red_add_v4(&g_dl[d * CH + q * 4], el);
    red_add_v4(&g_dr[d * CH + q * 4], er);
}

// ---------------- edge pass 2: ftr_raw[d] += r[s] * exp(sig(l_s+l_d)) -------
__global__ void __launch_bounds__(256) edge_ftr_kernel(const int* __restrict__ src,
                                                       const int* __restrict__ dst) {
    int warp = blockIdx.x * (blockDim.x >> 5) + (threadIdx.x >> 5);
    int e = warp * 2 + ((threadIdx.x >> 4) & 1);
    if (e >= ETOT) return;
    int q = threadIdx.x & 15;
    int s, d;
    if (e < NE) { s = src[e]; d = dst[e]; }
    else        { s = e - NE; d = s; }

    float4 ls = reinterpret_cast<const float4*>(g_l + s * CH)[q];
    float4 ld = reinterpret_cast<const float4*>(g_l + d * CH)[q];
    float4 rs = reinterpret_cast<const float4*>(g_r + s * CH)[q];

    float4 v = make_float4(rs.x * expsig(ls.x + ld.x),
                           rs.y * expsig(ls.y + ld.y),
                           rs.z * expsig(ls.z + ld.z),
                           rs.w * expsig(ls.w + ld.w));

    red_add_v4(&g_ftr[d * CH + q * 4], v);
}

// ---------------- node pass: normalize ftr by denominator ------------------
__global__ void scale_ftr_kernel() {
    int i = blockIdx.x * blockDim.x + threadIdx.x;
    if (i < NN * CH / 4) {
        float4 f = reinterpret_cast<float4*>(g_ftr)[i];
        float4 dd = reinterpret_cast<float4*>(g_dl)[i];
        f.x /= dd.x; f.y /= dd.y; f.z /= dd.z; f.w /= dd.w;
        reinterpret_cast<float4*>(g_ftr)[i] = f;
    }
}

// ---------------- edge pass 3: ftl_raw[d] += ftr[s] * exp(sig(r_s+r_d)) -----
__global__ void __launch_bounds__(256) edge_ftl_kernel(const int* __restrict__ src,
                                                       const int* __restrict__ dst) {
    int warp = blockIdx.x * (blockDim.x >> 5) + (threadIdx.x >> 5);
    int e = warp * 2 + ((threadIdx.x >> 4) & 1);
    if (e >= ETOT) return;
    int q = threadIdx.x & 15;
    int s, d;
    if (e < NE) { s = src[e]; d = dst[e]; }
    else        { s = e - NE; d = s; }

    float4 rs  = reinterpret_cast<const float4*>(g_r + s * CH)[q];
    float4 rd  = reinterpret_cast<const float4*>(g_r + d * CH)[q];
    float4 frs = reinterpret_cast<const float4*>(g_ftr + s * CH)[q];

    float4 v = make_float4(frs.x * expsig(rs.x + rd.x),
                           frs.y * expsig(rs.y + rd.y),
                           frs.z * expsig(rs.z + rd.z),
                           frs.w * expsig(rs.w + rd.w));

    red_add_v4(&g_ftl[d * CH + q * 4], v);
}

// ---------------- final: out = m0 * (ftl/dr) + res --------------------------
__global__ void final_kernel(const float* __restrict__ m, float* __restrict__ out) {
    int i = blockIdx.x * blockDim.x + threadIdx.x;
    if (i < NN * CH) {
        out[i] = __ldg(&m[i & 63]) * (g_ftl[i] / g_dr[i]) + g_res[i];
    }
}

extern "C" void kernel_launch(void* const* d_in, const int* in_sizes, int n_in,
                              void* d_out, int out_size) {
    const float* ndata = (const float*)d_in[0];
    const int*   src   = (const int*)d_in[1];
    const int*   dst   = (const int*)d_in[2];
    const float* W1    = (const float*)d_in[3];
    const float* b1    = (const float*)d_in[4];
    const float* W2    = (const float*)d_in[5];
    const float* b2    = (const float*)d_in[6];
    const float* Wres  = (const float*)d_in[7];
    const float* bres  = (const float*)d_in[8];
    const float* m     = (const float*)d_in[9];
    float* out = (float*)d_out;

    {
        int total = NN * CH / 4;
        zero_kernel<<<(total + 255) / 256, 256>>>();
    }
    node_proj_kernel<<<(NN + 3) / 4, 256>>>(ndata, W1, b1, W2, b2, Wres, bres);

    // edge passes: 2 edges per warp, 8 warps per block -> 16 edges per block
    int eblocks = (ETOT + 15) / 16;
    edge_denom_kernel<<<eblocks, 256>>>(src, dst);
    edge_ftr_kernel<<<eblocks, 256>>>(src, dst);
    {
        int total = NN * CH / 4;
        scale_ftr_kernel<<<(total + 255) / 256, 256>>>();
    }
    edge_ftl_kernel<<<eblocks, 256>>>(src, dst);

    final_kernel<<<(NN * CH + 255) / 256, 256>>>(m, out);
}

// round 3
// speedup vs baseline: 1.6529x; 1.2055x over previous
#include <cuda_runtime.h>

#define NN 50000
#define NE 800000
#define CH 64
#define ETOT (NE + NN)

// ---------------- scratch (device globals; no allocation allowed) ----------
__device__ float g_l[NN * CH];
__device__ float g_r[NN * CH];
__device__ float g_res[NN * CH];
__device__ float g_dl[NN * CH];
__device__ float g_dr[NN * CH];
__device__ float g_ftr[NN * CH];
__device__ float g_ftl[NN * CH];

__device__ __forceinline__ float expsig(float x) {
    // exp(sigmoid(x)); sigmoid in (0,1) so exp in (1,e): overflow-safe,
    // and exp(v)/sum == exp(v-mx)/sum(exp(v-mx)) exactly in math.
    return __expf(__frcp_rn(1.f + __expf(-x)));
}

__device__ __forceinline__ void red_add_v4(float* p, float4 v) {
    asm volatile("red.global.v4.f32.add [%0], {%1,%2,%3,%4};"
                 :: "l"(p), "f"(v.x), "f"(v.y), "f"(v.z), "f"(v.w)
                 : "memory");
}

// ---------------- node pass: minmax norm + three 64x64 GEMVs + zeroing -----
// 256 threads/block = 16 nodes/block; 16 threads per node; each thread owns
// 4 output features across all 3 matrices (float4 weight loads).
__global__ void __launch_bounds__(256) node_proj_kernel(
        const float* __restrict__ ndata,
        const float* __restrict__ W1,   const float* __restrict__ b1,
        const float* __restrict__ W2,   const float* __restrict__ b2,
        const float* __restrict__ Wres, const float* __restrict__ bres) {
    __shared__ float sx[16][CH];

    int t  = threadIdx.x;
    int ng = t >> 4;          // node within block: 0..15
    int q  = t & 15;          // feature quad: 0..15
    int n  = blockIdx.x * 16 + ng;
    bool valid = (n < NN);

    float4 v = valid ? reinterpret_cast<const float4*>(ndata + n * CH)[q]
                     : make_float4(0.f, 0.f, 0.f, 0.f);

    float mn = fminf(fminf(v.x, v.y), fminf(v.z, v.w));
    float mx = fmaxf(fmaxf(v.x, v.y), fmaxf(v.z, v.w));
    // butterfly within the 16-lane node group (lanes [0..15] / [16..31])
    #pragma unroll
    for (int off = 8; off > 0; off >>= 1) {
        mn = fminf(mn, __shfl_xor_sync(0xffffffffu, mn, off));
        mx = fmaxf(mx, __shfl_xor_sync(0xffffffffu, mx, off));
    }
    float inv = __frcp_rn(mx - mn + 1e-5f);
    sx[ng][q * 4 + 0] = (v.x - mn) * inv;
    sx[ng][q * 4 + 1] = (v.y - mn) * inv;
    sx[ng][q * 4 + 2] = (v.z - mn) * inv;
    sx[ng][q * 4 + 3] = (v.w - mn) * inv;
    __syncthreads();

    if (!valid) return;

    float4 a1 = __ldg(reinterpret_cast<const float4*>(b1)   + q);
    float4 a2 = __ldg(reinterpret_cast<const float4*>(b2)   + q);
    float4 ar = __ldg(reinterpret_cast<const float4*>(bres) + q);

    #pragma unroll
    for (int k = 0; k < CH; k++) {
        float xv = sx[ng][k];
        float4 w1 = __ldg(reinterpret_cast<const float4*>(W1   + k * CH) + q);
        float4 w2 = __ldg(reinterpret_cast<const float4*>(W2   + k * CH) + q);
        float4 wr = __ldg(reinterpret_cast<const float4*>(Wres + k * CH) + q);
        a1.x = fmaf(xv, w1.x, a1.x); a1.y = fmaf(xv, w1.y, a1.y);
        a1.z = fmaf(xv, w1.z, a1.z); a1.w = fmaf(xv, w1.w, a1.w);
        a2.x = fmaf(xv, w2.x, a2.x); a2.y = fmaf(xv, w2.y, a2.y);
        a2.z = fmaf(xv, w2.z, a2.z); a2.w = fmaf(xv, w2.w, a2.w);
        ar.x = fmaf(xv, wr.x, ar.x); ar.y = fmaf(xv, wr.y, ar.y);
        ar.z = fmaf(xv, wr.z, ar.z); ar.w = fmaf(xv, wr.w, ar.w);
    }
    reinterpret_cast<float4*>(g_l   + n * CH)[q] = a1;
    reinterpret_cast<float4*>(g_r   + n * CH)[q] = a2;
    reinterpret_cast<float4*>(g_res + n * CH)[q] = ar;

    // zero the accumulators for this node (replaces zero_kernel)
    float4 z = make_float4(0.f, 0.f, 0.f, 0.f);
    reinterpret_cast<float4*>(g_dl  + n * CH)[q] = z;
    reinterpret_cast<float4*>(g_dr  + n * CH)[q] = z;
    reinterpret_cast<float4*>(g_ftr + n * CH)[q] = z;
    reinterpret_cast<float4*>(g_ftl + n * CH)[q] = z;
}

// ---------------- fused edge pass A: denominators + raw ftr -----------------
// dl[d]  += exp(sig(l_s+l_d))            (softmax_l denominator)
// dr[d]  += exp(sig(r_s+r_d))            (softmax_r denominator)
// ftr[d] += r[s] * exp(sig(l_s+l_d))     (unnormalized; scaled by dl later)
// 2 edges per warp; 16 lanes per edge; float4 per lane.
__global__ void __launch_bounds__(256) edge_passA_kernel(const int* __restrict__ src,
                                                         const int* __restrict__ dst) {
    int warp = blockIdx.x * (blockDim.x >> 5) + (threadIdx.x >> 5);
    int e = warp * 2 + ((threadIdx.x >> 4) & 1);
    if (e >= ETOT) return;
    int q = threadIdx.x & 15;
    int s, d;
    if (e < NE) { s = src[e]; d = dst[e]; }
    else        { s = e - NE; d = s; }

    float4 ls = reinterpret_cast<const float4*>(g_l + s * CH)[q];
    float4 ld = reinterpret_cast<const float4*>(g_l + d * CH)[q];
    float4 rs = reinterpret_cast<const float4*>(g_r + s * CH)[q];
    float4 rd = reinterpret_cast<const float4*>(g_r + d * CH)[q];

    float4 el = make_float4(expsig(ls.x + ld.x), expsig(ls.y + ld.y),
                            expsig(ls.z + ld.z), expsig(ls.w + ld.w));
    float4 er = make_float4(expsig(rs.x + rd.x), expsig(rs.y + rd.y),
                            expsig(rs.z + rd.z), expsig(rs.w + rd.w));
    float4 fv = make_float4(rs.x * el.x, rs.y * el.y, rs.z * el.z, rs.w * el.w);

    red_add_v4(&g_dl [d * CH + q * 4], el);
    red_add_v4(&g_dr [d * CH + q * 4], er);
    red_add_v4(&g_ftr[d * CH + q * 4], fv);
}

// ---------------- node pass: normalize ftr by dl ----------------------------
__global__ void scale_ftr_kernel() {
    int i = blockIdx.x * blockDim.x + threadIdx.x;
    if (i < NN * CH / 4) {
        float4 f  = reinterpret_cast<float4*>(g_ftr)[i];
        float4 dd = reinterpret_cast<float4*>(g_dl)[i];
        f.x /= dd.x; f.y /= dd.y; f.z /= dd.z; f.w /= dd.w;
        reinterpret_cast<float4*>(g_ftr)[i] = f;
    }
}

// ---------------- edge pass B: ftl_raw[d] += ftr[s] * exp(sig(r_s+r_d)) -----
__global__ void __launch_bounds__(256) edge_passB_kernel(const int* __restrict__ src,
                                                         const int* __restrict__ dst) {
    int warp = blockIdx.x * (blockDim.x >> 5) + (threadIdx.x >> 5);
    int e = warp * 2 + ((threadIdx.x >> 4) & 1);
    if (e >= ETOT) return;
    int q = threadIdx.x & 15;
    int s, d;
    if (e < NE) { s = src[e]; d = dst[e]; }
    else        { s = e - NE; d = s; }

    float4 rs  = reinterpret_cast<const float4*>(g_r + s * CH)[q];
    float4 rd  = reinterpret_cast<const float4*>(g_r + d * CH)[q];
    float4 frs = reinterpret_cast<const float4*>(g_ftr + s * CH)[q];

    float4 v = make_float4(frs.x * expsig(rs.x + rd.x),
                           frs.y * expsig(rs.y + rd.y),
                           frs.z * expsig(rs.z + rd.z),
                           frs.w * expsig(rs.w + rd.w));

    red_add_v4(&g_ftl[d * CH + q * 4], v);
}

// ---------------- final: out = m0 * (ftl/dr) + res --------------------------
__global__ void final_kernel(const float* __restrict__ m, float* __restrict__ out) {
    int i = blockIdx.x * blockDim.x + threadIdx.x;
    if (i < NN * CH) {
        out[i] = __ldg(&m[i & 63]) * (g_ftl[i] / g_dr[i]) + g_res[i];
    }
}

extern "C" void kernel_launch(void* const* d_in, const int* in_sizes, int n_in,
                              void* d_out, int out_size) {
    const float* ndata = (const float*)d_in[0];
    const int*   src   = (const int*)d_in[1];
    const int*   dst   = (const int*)d_in[2];
    const float* W1    = (const float*)d_in[3];
    const float* b1    = (const float*)d_in[4];
    const float* W2    = (const float*)d_in[5];
    const float* b2    = (const float*)d_in[6];
    const float* Wres  = (const float*)d_in[7];
    const float* bres  = (const float*)d_in[8];
    const float* m     = (const float*)d_in[9];
    float* out = (float*)d_out;

    // node projections + accumulator zeroing
    node_proj_kernel<<<(NN + 15) / 16, 256>>>(ndata, W1, b1, W2, b2, Wres, bres);

    // edge passes: 2 edges per warp, 8 warps per block -> 16 edges per block
    int eblocks = (ETOT + 15) / 16;
    edge_passA_kernel<<<eblocks, 256>>>(src, dst);
    {
        int total = NN * CH / 4;
        scale_ftr_kernel<<<(total + 255) / 256, 256>>>();
    }
    edge_passB_kernel<<<eblocks, 256>>>(src, dst);

    final_kernel<<<(NN * CH + 255) / 256, 256>>>(m, out);
}

// round 4
// speedup vs baseline: 1.8350x; 1.1102x over previous
#include <cuda_runtime.h>

#define NN 50000
#define NE 800000
#define CH 64
#define ETOT (NE + NN)

// ---------------- scratch (device globals; no allocation allowed) ----------
__device__ float g_l[NN * CH];
__device__ float g_r[NN * CH];
__device__ float g_res[NN * CH];
__device__ float g_dl[NN * CH];
__device__ float g_dr[NN * CH];
__device__ float g_ftr[NN * CH];
__device__ float g_ftl[NN * CH];

__device__ __forceinline__ float fast_rcp(float x) {
    float r;
    asm("rcp.approx.f32 %0, %1;" : "=f"(r) : "f"(x));
    return r;
}

__device__ __forceinline__ float expsig(float x) {
    // exp(sigmoid(x)); sigmoid in (0,1) so exp in (1,e): overflow-safe,
    // and exp(v)/sum == exp(v-mx)/sum(exp(v-mx)) exactly in math.
    // rcp.approx: 2^-22 relative error, far inside tolerance.
    float u = __expf(-x);
    float s = fast_rcp(1.f + u);
    return __expf(s);
}

__device__ __forceinline__ void red_add_v4(float* p, float4 v) {
    asm volatile("red.global.v4.f32.add [%0], {%1,%2,%3,%4};"
                 :: "l"(p), "f"(v.x), "f"(v.y), "f"(v.z), "f"(v.w)
                 : "memory");
}

// ---------------- node pass: minmax norm + three 64x64 GEMVs + zeroing -----
__global__ void __launch_bounds__(256) node_proj_kernel(
        const float* __restrict__ ndata,
        const float* __restrict__ W1,   const float* __restrict__ b1,
        const float* __restrict__ W2,   const float* __restrict__ b2,
        const float* __restrict__ Wres, const float* __restrict__ bres) {
    __shared__ float sx[16][CH];

    int t  = threadIdx.x;
    int ng = t >> 4;          // node within block: 0..15
    int q  = t & 15;          // feature quad: 0..15
    int n  = blockIdx.x * 16 + ng;
    bool valid = (n < NN);

    float4 v = valid ? reinterpret_cast<const float4*>(ndata + n * CH)[q]
                     : make_float4(0.f, 0.f, 0.f, 0.f);

    float mn = fminf(fminf(v.x, v.y), fminf(v.z, v.w));
    float mx = fmaxf(fmaxf(v.x, v.y), fmaxf(v.z, v.w));
    #pragma unroll
    for (int off = 8; off > 0; off >>= 1) {
        mn = fminf(mn, __shfl_xor_sync(0xffffffffu, mn, off));
        mx = fmaxf(mx, __shfl_xor_sync(0xffffffffu, mx, off));
    }
    float inv = __frcp_rn(mx - mn + 1e-5f);   // exact: feeds output directly
    sx[ng][q * 4 + 0] = (v.x - mn) * inv;
    sx[ng][q * 4 + 1] = (v.y - mn) * inv;
    sx[ng][q * 4 + 2] = (v.z - mn) * inv;
    sx[ng][q * 4 + 3] = (v.w - mn) * inv;
    __syncthreads();

    if (!valid) return;

    float4 a1 = __ldg(reinterpret_cast<const float4*>(b1)   + q);
    float4 a2 = __ldg(reinterpret_cast<const float4*>(b2)   + q);
    float4 ar = __ldg(reinterpret_cast<const float4*>(bres) + q);

    #pragma unroll
    for (int k = 0; k < CH; k++) {
        float xv = sx[ng][k];
        float4 w1 = __ldg(reinterpret_cast<const float4*>(W1   + k * CH) + q);
        float4 w2 = __ldg(reinterpret_cast<const float4*>(W2   + k * CH) + q);
        float4 wr = __ldg(reinterpret_cast<const float4*>(Wres + k * CH) + q);
        a1.x = fmaf(xv, w1.x, a1.x); a1.y = fmaf(xv, w1.y, a1.y);
        a1.z = fmaf(xv, w1.z, a1.z); a1.w = fmaf(xv, w1.w, a1.w);
        a2.x = fmaf(xv, w2.x, a2.x); a2.y = fmaf(xv, w2.y, a2.y);
        a2.z = fmaf(xv, w2.z, a2.z); a2.w = fmaf(xv, w2.w, a2.w);
        ar.x = fmaf(xv, wr.x, ar.x); ar.y = fmaf(xv, wr.y, ar.y);
        ar.z = fmaf(xv, wr.z, ar.z); ar.w = fmaf(xv, wr.w, ar.w);
    }
    reinterpret_cast<float4*>(g_l   + n * CH)[q] = a1;
    reinterpret_cast<float4*>(g_r   + n * CH)[q] = a2;
    reinterpret_cast<float4*>(g_res + n * CH)[q] = ar;

    float4 z = make_float4(0.f, 0.f, 0.f, 0.f);
    reinterpret_cast<float4*>(g_dl  + n * CH)[q] = z;
    reinterpret_cast<float4*>(g_dr  + n * CH)[q] = z;
    reinterpret_cast<float4*>(g_ftr + n * CH)[q] = z;
    reinterpret_cast<float4*>(g_ftl + n * CH)[q] = z;
}

// ---------------- edge pass A: dl[d] += el ; ftr[d] += r[s]*el ---------------
// el = expsig(l_s + l_d). 3 gathers, 4 expsig, 2 REDs per thread.
__global__ void __launch_bounds__(256) edge_passA_kernel(const int* __restrict__ src,
                                                         const int* __restrict__ dst) {
    int warp = blockIdx.x * (blockDim.x >> 5) + (threadIdx.x >> 5);
    int e = warp * 2 + ((threadIdx.x >> 4) & 1);
    if (e >= ETOT) return;
    int q = threadIdx.x & 15;
    int s, d;
    if (e < NE) { s = src[e]; d = dst[e]; }
    else        { s = e - NE; d = s; }

    float4 ls = __ldg(reinterpret_cast<const float4*>(g_l + s * CH) + q);
    float4 ld = __ldg(reinterpret_cast<const float4*>(g_l + d * CH) + q);
    float4 rs = __ldg(reinterpret_cast<const float4*>(g_r + s * CH) + q);

    float4 el = make_float4(expsig(ls.x + ld.x), expsig(ls.y + ld.y),
                            expsig(ls.z + ld.z), expsig(ls.w + ld.w));
    float4 fv = make_float4(rs.x * el.x, rs.y * el.y, rs.z * el.z, rs.w * el.w);

    red_add_v4(&g_dl [d * CH + q * 4], el);
    red_add_v4(&g_ftr[d * CH + q * 4], fv);
}

// ---------------- node pass: normalize ftr by dl ----------------------------
__global__ void scale_ftr_kernel() {
    int i = blockIdx.x * blockDim.x + threadIdx.x;
    if (i < NN * CH / 4) {
        float4 f  = reinterpret_cast<float4*>(g_ftr)[i];
        float4 dd = reinterpret_cast<float4*>(g_dl)[i];
        f.x *= fast_rcp(dd.x); f.y *= fast_rcp(dd.y);
        f.z *= fast_rcp(dd.z); f.w *= fast_rcp(dd.w);
        reinterpret_cast<float4*>(g_ftr)[i] = f;
    }
}

// ---------------- edge pass B: dr[d] += er ; ftl[d] += ftr[s]*er -------------
// er = expsig(r_s + r_d). dr accumulated HERE (er already computed as the
// weight) instead of pass A — saves a gather + 4 expsig + a RED there.
__global__ void __launch_bounds__(256) edge_passB_kernel(const int* __restrict__ src,
                                                         const int* __restrict__ dst) {
    int warp = blockIdx.x * (blockDim.x >> 5) + (threadIdx.x >> 5);
    int e = warp * 2 + ((threadIdx.x >> 4) & 1);
    if (e >= ETOT) return;
    int q = threadIdx.x & 15;
    int s, d;
    if (e < NE) { s = src[e]; d = dst[e]; }
    else        { s = e - NE; d = s; }

    float4 rs  = __ldg(reinterpret_cast<const float4*>(g_r + s * CH) + q);
    float4 rd  = __ldg(reinterpret_cast<const float4*>(g_r + d * CH) + q);
    float4 frs = __ldg(reinterpret_cast<const float4*>(g_ftr + s * CH) + q);

    float4 er = make_float4(expsig(rs.x + rd.x), expsig(rs.y + rd.y),
                            expsig(rs.z + rd.z), expsig(rs.w + rd.w));
    float4 v  = make_float4(frs.x * er.x, frs.y * er.y,
                            frs.z * er.z, frs.w * er.w);

    red_add_v4(&g_dr [d * CH + q * 4], er);
    red_add_v4(&g_ftl[d * CH + q * 4], v);
}

// ---------------- final: out = m0 * (ftl/dr) + res --------------------------
__global__ void final_kernel(const float* __restrict__ m, float* __restrict__ out) {
    int i = blockIdx.x * blockDim.x + threadIdx.x;
    if (i < NN * CH) {
        out[i] = __ldg(&m[i & 63]) * (g_ftl[i] * fast_rcp(g_dr[i])) + g_res[i];
    }
}

extern "C" void kernel_launch(void* const* d_in, const int* in_sizes, int n_in,
                              void* d_out, int out_size) {
    const float* ndata = (const float*)d_in[0];
    const int*   src   = (const int*)d_in[1];
    const int*   dst   = (const int*)d_in[2];
    const float* W1    = (const float*)d_in[3];
    const float* b1    = (const float*)d_in[4];
    const float* W2    = (const float*)d_in[5];
    const float* b2    = (const float*)d_in[6];
    const float* Wres  = (const float*)d_in[7];
    const float* bres  = (const float*)d_in[8];
    const float* m     = (const float*)d_in[9];
    float* out = (float*)d_out;

    node_proj_kernel<<<(NN + 15) / 16, 256>>>(ndata, W1, b1, W2, b2, Wres, bres);

    int eblocks = (ETOT + 15) / 16;
    edge_passA_kernel<<<eblocks, 256>>>(src, dst);
    {
        int total = NN * CH / 4;
        scale_ftr_kernel<<<(total + 255) / 256, 256>>>();
    }
    edge_passB_kernel<<<eblocks, 256>>>(src, dst);

    final_kernel<<<(NN * CH + 255) / 256, 256>>>(m, out);
}

// round 5
// speedup vs baseline: 1.8655x; 1.0166x over previous
#include <cuda_runtime.h>
#include <cuda_fp16.h>

#define NN 50000
#define NE 800000
#define CH 64
#define ETOT (NE + NN)

// ---------------- scratch (device globals; no allocation allowed) ----------
__device__ __half g_lh[NN * CH];   // l projection, half (logits only)
__device__ __half g_rh[NN * CH];   // r projection, half (logits only)
__device__ float  g_r  [NN * CH];  // r projection, fp32 (values in pass A)
__device__ float  g_res[NN * CH];
__device__ float  g_dl [NN * CH];
__device__ float  g_dr [NN * CH];
__device__ float  g_ftr[NN * CH];
__device__ float  g_ftl[NN * CH];

__device__ __forceinline__ float fast_rcp(float x) {
    float r;
    asm("rcp.approx.f32 %0, %1;" : "=f"(r) : "f"(x));
    return r;
}

__device__ __forceinline__ float expsig(float x) {
    // exp(sigmoid(x)); sigmoid in (0,1) so exp in (1,e): overflow-safe,
    // and exp(v)/sum == exp(v-mx)/sum(exp(v-mx)) exactly in math.
    float u = __expf(-x);
    float s = fast_rcp(1.f + u);
    return __expf(s);
}

__device__ __forceinline__ void red_add_v4(float* p, float4 v) {
    asm volatile("red.global.v4.f32.add [%0], {%1,%2,%3,%4};"
                 :: "l"(p), "f"(v.x), "f"(v.y), "f"(v.z), "f"(v.w)
                 : "memory");
}

// load 4 halfs (8B) at feature-quad q of node row n, convert to float4
__device__ __forceinline__ float4 ldg_half4(const __half* base, int n, int q) {
    float2 raw = __ldg(reinterpret_cast<const float2*>(base + n * CH) + q);
    __half2 h0 = *reinterpret_cast<__half2*>(&raw.x);
    __half2 h1 = *reinterpret_cast<__half2*>(&raw.y);
    float2 f0 = __half22float2(h0);
    float2 f1 = __half22float2(h1);
    return make_float4(f0.x, f0.y, f1.x, f1.y);
}

// ---------------- node pass: minmax norm + three 64x64 GEMVs + zeroing -----
__global__ void __launch_bounds__(256) node_proj_kernel(
        const float* __restrict__ ndata,
        const float* __restrict__ W1,   const float* __restrict__ b1,
        const float* __restrict__ W2,   const float* __restrict__ b2,
        const float* __restrict__ Wres, const float* __restrict__ bres) {
    __shared__ float sx[16][CH];

    int t  = threadIdx.x;
    int ng = t >> 4;          // node within block: 0..15
    int q  = t & 15;          // feature quad: 0..15
    int n  = blockIdx.x * 16 + ng;
    bool valid = (n < NN);

    float4 v = valid ? reinterpret_cast<const float4*>(ndata + n * CH)[q]
                     : make_float4(0.f, 0.f, 0.f, 0.f);

    float mn = fminf(fminf(v.x, v.y), fminf(v.z, v.w));
    float mx = fmaxf(fmaxf(v.x, v.y), fmaxf(v.z, v.w));
    #pragma unroll
    for (int off = 8; off > 0; off >>= 1) {
        mn = fminf(mn, __shfl_xor_sync(0xffffffffu, mn, off));
        mx = fmaxf(mx, __shfl_xor_sync(0xffffffffu, mx, off));
    }
    float inv = __frcp_rn(mx - mn + 1e-5f);   // exact: feeds output directly
    sx[ng][q * 4 + 0] = (v.x - mn) * inv;
    sx[ng][q * 4 + 1] = (v.y - mn) * inv;
    sx[ng][q * 4 + 2] = (v.z - mn) * inv;
    sx[ng][q * 4 + 3] = (v.w - mn) * inv;
    __syncthreads();

    if (!valid) return;

    float4 a1 = __ldg(reinterpret_cast<const float4*>(b1)   + q);
    float4 a2 = __ldg(reinterpret_cast<const float4*>(b2)   + q);
    float4 ar = __ldg(reinterpret_cast<const float4*>(bres) + q);

    #pragma unroll
    for (int k = 0; k < CH; k++) {
        float xv = sx[ng][k];
        float4 w1 = __ldg(reinterpret_cast<const float4*>(W1   + k * CH) + q);
        float4 w2 = __ldg(reinterpret_cast<const float4*>(W2   + k * CH) + q);
        float4 wr = __ldg(reinterpret_cast<const float4*>(Wres + k * CH) + q);
        a1.x = fmaf(xv, w1.x, a1.x); a1.y = fmaf(xv, w1.y, a1.y);
        a1.z = fmaf(xv, w1.z, a1.z); a1.w = fmaf(xv, w1.w, a1.w);
        a2.x = fmaf(xv, w2.x, a2.x); a2.y = fmaf(xv, w2.y, a2.y);
        a2.z = fmaf(xv, w2.z, a2.z); a2.w = fmaf(xv, w2.w, a2.w);
        ar.x = fmaf(xv, wr.x, ar.x); ar.y = fmaf(xv, wr.y, ar.y);
        ar.z = fmaf(xv, wr.z, ar.z); ar.w = fmaf(xv, wr.w, ar.w);
    }

    // l as half only; r as fp32 + half
    __half2 l01 = __floats2half2_rn(a1.x, a1.y);
    __half2 l23 = __floats2half2_rn(a1.z, a1.w);
    __half2 r01 = __floats2half2_rn(a2.x, a2.y);
    __half2 r23 = __floats2half2_rn(a2.z, a2.w);
    float2 lhp, rhp;
    *reinterpret_cast<__half2*>(&lhp.x) = l01;
    *reinterpret_cast<__half2*>(&lhp.y) = l23;
    *reinterpret_cast<__half2*>(&rhp.x) = r01;
    *reinterpret_cast<__half2*>(&rhp.y) = r23;
    reinterpret_cast<float2*>(g_lh + n * CH)[q] = lhp;
    reinterpret_cast<float2*>(g_rh + n * CH)[q] = rhp;

    reinterpret_cast<float4*>(g_r   + n * CH)[q] = a2;
    reinterpret_cast<float4*>(g_res + n * CH)[q] = ar;

    float4 z = make_float4(0.f, 0.f, 0.f, 0.f);
    reinterpret_cast<float4*>(g_dl  + n * CH)[q] = z;
    reinterpret_cast<float4*>(g_dr  + n * CH)[q] = z;
    reinterpret_cast<float4*>(g_ftr + n * CH)[q] = z;
    reinterpret_cast<float4*>(g_ftl + n * CH)[q] = z;
}

// ---------------- edge pass A: dl[d] += el ; ftr[d] += r[s]*el ---------------
// el = expsig(l_s + l_d), logits gathered in half (128B/row vs 256B).
__global__ void __launch_bounds__(256) edge_passA_kernel(const int* __restrict__ src,
                                                         const int* __restrict__ dst) {
    int warp = blockIdx.x * (blockDim.x >> 5) + (threadIdx.x >> 5);
    int e = warp * 2 + ((threadIdx.x >> 4) & 1);
    if (e >= ETOT) return;
    int q = threadIdx.x & 15;
    int s, d;
    if (e < NE) { s = src[e]; d = dst[e]; }
    else        { s = e - NE; d = s; }

    float4 ls = ldg_half4(g_lh, s, q);
    float4 ld = ldg_half4(g_lh, d, q);
    float4 rs = __ldg(reinterpret_cast<const float4*>(g_r + s * CH) + q);

    float4 el = make_float4(expsig(ls.x + ld.x), expsig(ls.y + ld.y),
                            expsig(ls.z + ld.z), expsig(ls.w + ld.w));
    float4 fv = make_float4(rs.x * el.x, rs.y * el.y, rs.z * el.z, rs.w * el.w);

    red_add_v4(&g_dl [d * CH + q * 4], el);
    red_add_v4(&g_ftr[d * CH + q * 4], fv);
}

// ---------------- node pass: normalize ftr by dl ----------------------------
__global__ void scale_ftr_kernel() {
    int i = blockIdx.x * blockDim.x + threadIdx.x;
    if (i < NN * CH / 4) {
        float4 f  = reinterpret_cast<float4*>(g_ftr)[i];
        float4 dd = reinterpret_cast<float4*>(g_dl)[i];
        f.x *= fast_rcp(dd.x); f.y *= fast_rcp(dd.y);
        f.z *= fast_rcp(dd.z); f.w *= fast_rcp(dd.w);
        reinterpret_cast<float4*>(g_ftr)[i] = f;
    }
}

// ---------------- edge pass B: dr[d] += er ; ftl[d] += ftr[s]*er -------------
// er = expsig(r_s + r_d), logits gathered in half.
__global__ void __launch_bounds__(256) edge_passB_kernel(const int* __restrict__ src,
                                                         const int* __restrict__ dst) {
    int warp = blockIdx.x * (blockDim.x >> 5) + (threadIdx.x >> 5);
    int e = warp * 2 + ((threadIdx.x >> 4) & 1);
    if (e >= ETOT) return;
    int q = threadIdx.x & 15;
    int s, d;
    if (e < NE) { s = src[e]; d = dst[e]; }
    else        { s = e - NE; d = s; }

    float4 rs  = ldg_half4(g_rh, s, q);
    float4 rd  = ldg_half4(g_rh, d, q);
    float4 frs = __ldg(reinterpret_cast<const float4*>(g_ftr + s * CH) + q);

    float4 er = make_float4(expsig(rs.x + rd.x), expsig(rs.y + rd.y),
                            expsig(rs.z + rd.z), expsig(rs.w + rd.w));
    float4 v  = make_float4(frs.x * er.x, frs.y * er.y,
                            frs.z * er.z, frs.w * er.w);

    red_add_v4(&g_dr [d * CH + q * 4], er);
    red_add_v4(&g_ftl[d * CH + q * 4], v);
}

// ---------------- final: out = m0 * (ftl/dr) + res --------------------------
__global__ void final_kernel(const float* __restrict__ m, float* __restrict__ out) {
    int i = blockIdx.x * blockDim.x + threadIdx.x;
    if (i < NN * CH) {
        out[i] = __ldg(&m[i & 63]) * (g_ftl[i] * fast_rcp(g_dr[i])) + g_res[i];
    }
}

extern "C" void kernel_launch(void* const* d_in, const int* in_sizes, int n_in,
                              void* d_out, int out_size) {
    const float* ndata = (const float*)d_in[0];
    const int*   src   = (const int*)d_in[1];
    const int*   dst   = (const int*)d_in[2];
    const float* W1    = (const float*)d_in[3];
    const float* b1    = (const float*)d_in[4];
    const float* W2    = (const float*)d_in[5];
    const float* b2    = (const float*)d_in[6];
    const float* Wres  = (const float*)d_in[7];
    const float* bres  = (const float*)d_in[8];
    const float* m     = (const float*)d_in[9];
    float* out = (float*)d_out;

    node_proj_kernel<<<(NN + 15) / 16, 256>>>(ndata, W1, b1, W2, b2, Wres, bres);

    int eblocks = (ETOT + 15) / 16;
    edge_passA_kernel<<<eblocks, 256>>>(src, dst);
    {
        int total = NN * CH / 4;
        scale_ftr_kernel<<<(total + 255) / 256, 256>>>();
    }
    edge_passB_kernel<<<eblocks, 256>>>(src, dst);

    final_kernel<<<(NN * CH + 255) / 256, 256>>>(m, out);
}

// round 6
// speedup vs baseline: 2.6087x; 1.3984x over previous
#include <cuda_runtime.h>
#include <cuda_fp16.h>

#define NN 50000
#define NE 800000
#define CH 64
#define ETOT (NE + NN)
#define NBLK ((NN + 255) / 256)   // 196 scan blocks

// ---------------- scratch (device globals; no allocation allowed) ----------
__device__ __half g_lh[NN * CH];   // l projection, half (logits only)
__device__ __half g_rh[NN * CH];   // r projection, half (logits only)
__device__ float  g_r  [NN * CH];  // r projection, fp32 (values in pass A)
__device__ float  g_res[NN * CH];
__device__ float  g_ftr[NN * CH];
// CSR build
__device__ int g_cnt[NN + 1];      // histogram, then reused as nothing
__device__ int g_off[NN + 1];      // CSR offsets
__device__ int g_cur[NN];          // scatter cursors
__device__ int g_bsum[NBLK];       // per-block sums
__device__ int g_bscan[NBLK];      // scanned block sums
__device__ int g_ssrc[ETOT];       // src node id per dst-sorted edge

__device__ __forceinline__ float fast_rcp(float x) {
    float r;
    asm("rcp.approx.f32 %0, %1;" : "=f"(r) : "f"(x));
    return r;
}

__device__ __forceinline__ float expsig(float x) {
    // exp(sigmoid(x)); sigmoid in (0,1) so exp in (1,e): overflow-safe,
    // and exp(v)/sum == exp(v-mx)/sum(exp(v-mx)) exactly in math.
    float u = __expf(-x);
    float s = fast_rcp(1.f + u);
    return __expf(s);
}

// load 4 halfs (8B) at feature-quad q of node row n, convert to float4
__device__ __forceinline__ float4 ldg_half4(const __half* base, int n, int q) {
    float2 raw = __ldg(reinterpret_cast<const float2*>(base + n * CH) + q);
    __half2 h0 = *reinterpret_cast<__half2*>(&raw.x);
    __half2 h1 = *reinterpret_cast<__half2*>(&raw.y);
    float2 f0 = __half22float2(h0);
    float2 f1 = __half22float2(h1);
    return make_float4(f0.x, f0.y, f1.x, f1.y);
}

// ================= node pass: minmax + 3 GEMVs, 2 nodes per thread =========
// 256 threads/block = 32 nodes/block; 16 threads per node pair (n, n+16).
__global__ void __launch_bounds__(256) node_proj_kernel(
        const float* __restrict__ ndata,
        const float* __restrict__ W1,   const float* __restrict__ b1,
        const float* __restrict__ W2,   const float* __restrict__ b2,
        const float* __restrict__ Wres, const float* __restrict__ bres) {
    __shared__ float sx[32][CH];

    int t  = threadIdx.x;
    int g  = t >> 4;          // group 0..15
    int q  = t & 15;          // feature quad
    int n0 = blockIdx.x * 32 + g;
    int n1 = n0 + 16;
    bool v0 = (n0 < NN), v1 = (n1 < NN);

    float4 x0 = v0 ? reinterpret_cast<const float4*>(ndata + n0 * CH)[q]
                   : make_float4(0.f, 0.f, 0.f, 0.f);
    float4 x1 = v1 ? reinterpret_cast<const float4*>(ndata + n1 * CH)[q]
                   : make_float4(0.f, 0.f, 0.f, 0.f);

    float mn0 = fminf(fminf(x0.x, x0.y), fminf(x0.z, x0.w));
    float mx0 = fmaxf(fmaxf(x0.x, x0.y), fmaxf(x0.z, x0.w));
    float mn1 = fminf(fminf(x1.x, x1.y), fminf(x1.z, x1.w));
    float mx1 = fmaxf(fmaxf(x1.x, x1.y), fmaxf(x1.z, x1.w));
    #pragma unroll
    for (int off = 8; off > 0; off >>= 1) {
        mn0 = fminf(mn0, __shfl_xor_sync(0xffffffffu, mn0, off));
        mx0 = fmaxf(mx0, __shfl_xor_sync(0xffffffffu, mx0, off));
        mn1 = fminf(mn1, __shfl_xor_sync(0xffffffffu, mn1, off));
        mx1 = fmaxf(mx1, __shfl_xor_sync(0xffffffffu, mx1, off));
    }
    float inv0 = __frcp_rn(mx0 - mn0 + 1e-5f);
    float inv1 = __frcp_rn(mx1 - mn1 + 1e-5f);
    sx[g][q*4+0] = (x0.x-mn0)*inv0; sx[g][q*4+1] = (x0.y-mn0)*inv0;
    sx[g][q*4+2] = (x0.z-mn0)*inv0; sx[g][q*4+3] = (x0.w-mn0)*inv0;
    sx[g+16][q*4+0] = (x1.x-mn1)*inv1; sx[g+16][q*4+1] = (x1.y-mn1)*inv1;
    sx[g+16][q*4+2] = (x1.z-mn1)*inv1; sx[g+16][q*4+3] = (x1.w-mn1)*inv1;
    __syncthreads();

    if (!v0) return;

    float4 bb1 = __ldg(reinterpret_cast<const float4*>(b1)   + q);
    float4 bb2 = __ldg(reinterpret_cast<const float4*>(b2)   + q);
    float4 bbr = __ldg(reinterpret_cast<const float4*>(bres) + q);
    float4 a1_0 = bb1, a2_0 = bb2, ar_0 = bbr;
    float4 a1_1 = bb1, a2_1 = bb2, ar_1 = bbr;

    #pragma unroll
    for (int k = 0; k < CH; k++) {
        float4 w1 = __ldg(reinterpret_cast<const float4*>(W1   + k * CH) + q);
        float4 w2 = __ldg(reinterpret_cast<const float4*>(W2   + k * CH) + q);
        float4 wr = __ldg(reinterpret_cast<const float4*>(Wres + k * CH) + q);
        float xa = sx[g][k];
        float xb = sx[g+16][k];
        a1_0.x = fmaf(xa,w1.x,a1_0.x); a1_0.y = fmaf(xa,w1.y,a1_0.y);
        a1_0.z = fmaf(xa,w1.z,a1_0.z); a1_0.w = fmaf(xa,w1.w,a1_0.w);
        a2_0.x = fmaf(xa,w2.x,a2_0.x); a2_0.y = fmaf(xa,w2.y,a2_0.y);
        a2_0.z = fmaf(xa,w2.z,a2_0.z); a2_0.w = fmaf(xa,w2.w,a2_0.w);
        ar_0.x = fmaf(xa,wr.x,ar_0.x); ar_0.y = fmaf(xa,wr.y,ar_0.y);
        ar_0.z = fmaf(xa,wr.z,ar_0.z); ar_0.w = fmaf(xa,wr.w,ar_0.w);
        a1_1.x = fmaf(xb,w1.x,a1_1.x); a1_1.y = fmaf(xb,w1.y,a1_1.y);
        a1_1.z = fmaf(xb,w1.z,a1_1.z); a1_1.w = fmaf(xb,w1.w,a1_1.w);
        a2_1.x = fmaf(xb,w2.x,a2_1.x); a2_1.y = fmaf(xb,w2.y,a2_1.y);
        a2_1.z = fmaf(xb,w2.z,a2_1.z); a2_1.w = fmaf(xb,w2.w,a2_1.w);
        ar_1.x = fmaf(xb,wr.x,ar_1.x); ar_1.y = fmaf(xb,wr.y,ar_1.y);
        ar_1.z = fmaf(xb,wr.z,ar_1.z); ar_1.w = fmaf(xb,wr.w,ar_1.w);
    }

    // store node n0
    {
        __half2 l01 = __floats2half2_rn(a1_0.x, a1_0.y);
        __half2 l23 = __floats2half2_rn(a1_0.z, a1_0.w);
        __half2 r01 = __floats2half2_rn(a2_0.x, a2_0.y);
        __half2 r23 = __floats2half2_rn(a2_0.z, a2_0.w);
        float2 lhp, rhp;
        *reinterpret_cast<__half2*>(&lhp.x) = l01;
        *reinterpret_cast<__half2*>(&lhp.y) = l23;
        *reinterpret_cast<__half2*>(&rhp.x) = r01;
        *reinterpret_cast<__half2*>(&rhp.y) = r23;
        reinterpret_cast<float2*>(g_lh + n0 * CH)[q] = lhp;
        reinterpret_cast<float2*>(g_rh + n0 * CH)[q] = rhp;
        reinterpret_cast<float4*>(g_r   + n0 * CH)[q] = a2_0;
        reinterpret_cast<float4*>(g_res + n0 * CH)[q] = ar_0;
    }
    if (v1) {
        __half2 l01 = __floats2half2_rn(a1_1.x, a1_1.y);
        __half2 l23 = __floats2half2_rn(a1_1.z, a1_1.w);
        __half2 r01 = __floats2half2_rn(a2_1.x, a2_1.y);
        __half2 r23 = __floats2half2_rn(a2_1.z, a2_1.w);
        float2 lhp, rhp;
        *reinterpret_cast<__half2*>(&lhp.x) = l01;
        *reinterpret_cast<__half2*>(&lhp.y) = l23;
        *reinterpret_cast<__half2*>(&rhp.x) = r01;
        *reinterpret_cast<__half2*>(&rhp.y) = r23;
        reinterpret_cast<float2*>(g_lh + n1 * CH)[q] = lhp;
        reinterpret_cast<float2*>(g_rh + n1 * CH)[q] = rhp;
        reinterpret_cast<float4*>(g_r   + n1 * CH)[q] = a2_1;
        reinterpret_cast<float4*>(g_res + n1 * CH)[q] = ar_1;
    }
}

// ================= CSR build =================================================
__global__ void init_cnt_kernel() {
    int i = blockIdx.x * blockDim.x + threadIdx.x;
    if (i <= NN) g_cnt[i] = 0;
}

__global__ void hist_kernel(const int* __restrict__ dst) {
    int e = blockIdx.x * blockDim.x + threadIdx.x;
    if (e >= ETOT) return;
    int d = (e < NE) ? dst[e] : (e - NE);
    atomicAdd(&g_cnt[d], 1);
}

// S1: per-block sums of 256 counts
__global__ void scan1_kernel() {
    __shared__ int sm[256];
    int t = threadIdx.x;
    int i = blockIdx.x * 256 + t;
    sm[t] = (i < NN) ? g_cnt[i] : 0;
    __syncthreads();
    #pragma unroll
    for (int o = 128; o > 0; o >>= 1) {
        if (t < o) sm[t] += sm[t + o];
        __syncthreads();
    }
    if (t == 0) g_bsum[blockIdx.x] = sm[0];
}

// S2: exclusive scan of the NBLK block sums (single block)
__global__ void scan2_kernel() {
    __shared__ int sm[256];
    int t = threadIdx.x;
    int v = (t < NBLK) ? g_bsum[t] : 0;
    sm[t] = v;
    __syncthreads();
    #pragma unroll
    for (int o = 1; o < 256; o <<= 1) {
        int add = (t >= o) ? sm[t - o] : 0;
        __syncthreads();
        sm[t] += add;
        __syncthreads();
    }
    if (t < NBLK) g_bscan[t] = sm[t] - v;   // exclusive
}

// S3: per-block exclusive scan + base; write off and cursor
__global__ void scan3_kernel() {
    __shared__ int sm[256];
    int t = threadIdx.x;
    int i = blockIdx.x * 256 + t;
    int v = (i < NN) ? g_cnt[i] : 0;
    sm[t] = v;
    __syncthreads();
    #pragma unroll
    for (int o = 1; o < 256; o <<= 1) {
        int add = (t >= o) ? sm[t - o] : 0;
        __syncthreads();
        sm[t] += add;
        __syncthreads();
    }
    if (i < NN) {
        int off = g_bscan[blockIdx.x] + sm[t] - v;
        g_off[i] = off;
        g_cur[i] = off;
    }
    if (i == 0) g_off[NN] = ETOT;
}

__global__ void scatter_kernel(const int* __restrict__ src,
                               const int* __restrict__ dst) {
    int e = blockIdx.x * blockDim.x + threadIdx.x;
    if (e >= ETOT) return;
    int s, d;
    if (e < NE) { s = src[e]; d = dst[e]; }
    else        { s = e - NE; d = s; }
    int pos = atomicAdd(&g_cur[d], 1);
    g_ssrc[pos] = s;
}

// ================= agg pass A: ftr[n] = sum(r[s]*el) / sum(el) ===============
// el = expsig(l_s + l_n). One 16-lane group per node; no atomics.
__global__ void __launch_bounds__(256) aggA_kernel() {
    int n = blockIdx.x * 16 + (threadIdx.x >> 4);
    if (n >= NN) return;
    int q = threadIdx.x & 15;

    float4 ldq = ldg_half4(g_lh, n, q);
    int i0 = __ldg(&g_off[n]);
    int i1 = __ldg(&g_off[n + 1]);

    float4 esum = make_float4(0.f, 0.f, 0.f, 0.f);
    float4 acc  = make_float4(0.f, 0.f, 0.f, 0.f);

    int i = i0;
    for (; i + 2 <= i1; i += 2) {
        int s0 = __ldg(&g_ssrc[i]);
        int s1 = __ldg(&g_ssrc[i + 1]);
        float4 ls0 = ldg_half4(g_lh, s0, q);
        float4 ls1 = ldg_half4(g_lh, s1, q);
        float4 rs0 = __ldg(reinterpret_cast<const float4*>(g_r + s0 * CH) + q);
        float4 rs1 = __ldg(reinterpret_cast<const float4*>(g_r + s1 * CH) + q);
        float4 e0 = make_float4(expsig(ls0.x+ldq.x), expsig(ls0.y+ldq.y),
                                expsig(ls0.z+ldq.z), expsig(ls0.w+ldq.w));
        float4 e1 = make_float4(expsig(ls1.x+ldq.x), expsig(ls1.y+ldq.y),
                                expsig(ls1.z+ldq.z), expsig(ls1.w+ldq.w));
        esum.x += e0.x + e1.x; esum.y += e0.y + e1.y;
        esum.z += e0.z + e1.z; esum.w += e0.w + e1.w;
        acc.x = fmaf(rs0.x, e0.x, acc.x); acc.x = fmaf(rs1.x, e1.x, acc.x);
        acc.y = fmaf(rs0.y, e0.y, acc.y); acc.y = fmaf(rs1.y, e1.y, acc.y);
        acc.z = fmaf(rs0.z, e0.z, acc.z); acc.z = fmaf(rs1.z, e1.z, acc.z);
        acc.w = fmaf(rs0.w, e0.w, acc.w); acc.w = fmaf(rs1.w, e1.w, acc.w);
    }
    if (i < i1) {
        int s0 = __ldg(&g_ssrc[i]);
        float4 ls0 = ldg_half4(g_lh, s0, q);
        float4 rs0 = __ldg(reinterpret_cast<const float4*>(g_r + s0 * CH) + q);
        float4 e0 = make_float4(expsig(ls0.x+ldq.x), expsig(ls0.y+ldq.y),
                                expsig(ls0.z+ldq.z), expsig(ls0.w+ldq.w));
        esum.x += e0.x; esum.y += e0.y; esum.z += e0.z; esum.w += e0.w;
        acc.x = fmaf(rs0.x, e0.x, acc.x); acc.y = fmaf(rs0.y, e0.y, acc.y);
        acc.z = fmaf(rs0.z, e0.z, acc.z); acc.w = fmaf(rs0.w, e0.w, acc.w);
    }

    acc.x *= fast_rcp(esum.x); acc.y *= fast_rcp(esum.y);
    acc.z *= fast_rcp(esum.z); acc.w *= fast_rcp(esum.w);
    reinterpret_cast<float4*>(g_ftr + n * CH)[q] = acc;
}

// ================= agg pass B: out = m0*(sum(ftr[s]*er)/sum(er)) + res =======
__global__ void __launch_bounds__(256) aggB_kernel(const float* __restrict__ m,
                                                   float* __restrict__ out) {
    int n = blockIdx.x * 16 + (threadIdx.x >> 4);
    if (n >= NN) return;
    int q = threadIdx.x & 15;

    float4 rdq = ldg_half4(g_rh, n, q);
    int i0 = __ldg(&g_off[n]);
    int i1 = __ldg(&g_off[n + 1]);

    float4 esum = make_float4(0.f, 0.f, 0.f, 0.f);
    float4 acc  = make_float4(0.f, 0.f, 0.f, 0.f);

    int i = i0;
    for (; i + 2 <= i1; i += 2) {
        int s0 = __ldg(&g_ssrc[i]);
        int s1 = __ldg(&g_ssrc[i + 1]);
        float4 rs0 = ldg_half4(g_rh, s0, q);
        float4 rs1 = ldg_half4(g_rh, s1, q);
        float4 f0 = __ldg(reinterpret_cast<const float4*>(g_ftr + s0 * CH) + q);
        float4 f1 = __ldg(reinterpret_cast<const float4*>(g_ftr + s1 * CH) + q);
        float4 e0 = make_float4(expsig(rs0.x+rdq.x), expsig(rs0.y+rdq.y),
                                expsig(rs0.z+rdq.z), expsig(rs0.w+rdq.w));
        float4 e1 = make_float4(expsig(rs1.x+rdq.x), expsig(rs1.y+rdq.y),
                                expsig(rs1.z+rdq.z), expsig(rs1.w+rdq.w));
        esum.x += e0.x + e1.x; esum.y += e0.y + e1.y;
        esum.z += e0.z + e1.z; esum.w += e0.w + e1.w;
        acc.x = fmaf(f0.x, e0.x, acc.x); acc.x = fmaf(f1.x, e1.x, acc.x);
        acc.y = fmaf(f0.y, e0.y, acc.y); acc.y = fmaf(f1.y, e1.y, acc.y);
        acc.z = fmaf(f0.z, e0.z, acc.z); acc.z = fmaf(f1.z, e1.z, acc.z);
        acc.w = fmaf(f0.w, e0.w, acc.w); acc.w = fmaf(f1.w, e1.w, acc.w);
    }
    if (i < i1) {
        int s0 = __ldg(&g_ssrc[i]);
        float4 rs0 = ldg_half4(g_rh, s0, q);
        float4 f0 = __ldg(reinterpret_cast<const float4*>(g_ftr + s0 * CH) + q);
        float4 e0 = make_float4(expsig(rs0.x+rdq.x), expsig(rs0.y+rdq.y),
                                expsig(rs0.z+rdq.z), expsig(rs0.w+rdq.w));
        esum.x += e0.x; esum.y += e0.y; esum.z += e0.z; esum.w += e0.w;
        acc.x = fmaf(f0.x, e0.x, acc.x); acc.y = fmaf(f0.y, e0.y, acc.y);
        acc.z = fmaf(f0.z, e0.z, acc.z); acc.w = fmaf(f0.w, e0.w, acc.w);
    }

    float4 mv = __ldg(reinterpret_cast<const float4*>(m) + q);
    float4 rv = __ldg(reinterpret_cast<const float4*>(g_res + n * CH) + q);
    float4 o;
    o.x = fmaf(mv.x, acc.x * fast_rcp(esum.x), rv.x);
    o.y = fmaf(mv.y, acc.y * fast_rcp(esum.y), rv.y);
    o.z = fmaf(mv.z, acc.z * fast_rcp(esum.z), rv.z);
    o.w = fmaf(mv.w, acc.w * fast_rcp(esum.w), rv.w);
    reinterpret_cast<float4*>(out + n * CH)[q] = o;
}

extern "C" void kernel_launch(void* const* d_in, const int* in_sizes, int n_in,
                              void* d_out, int out_size) {
    const float* ndata = (const float*)d_in[0];
    const int*   src   = (const int*)d_in[1];
    const int*   dst   = (const int*)d_in[2];
    const float* W1    = (const float*)d_in[3];
    const float* b1    = (const float*)d_in[4];
    const float* W2    = (const float*)d_in[5];
    const float* b2    = (const float*)d_in[6];
    const float* Wres  = (const float*)d_in[7];
    const float* bres  = (const float*)d_in[8];
    const float* m     = (const float*)d_in[9];
    float* out = (float*)d_out;

    // node projections (independent of CSR build — overlaps in graph order)
    node_proj_kernel<<<(NN + 31) / 32, 256>>>(ndata, W1, b1, W2, b2, Wres, bres);

    // CSR build
    init_cnt_kernel<<<(NN + 256) / 256, 256>>>();
    hist_kernel<<<(ETOT + 255) / 256, 256>>>(dst);
    scan1_kernel<<<NBLK, 256>>>();
    scan2_kernel<<<1, 256>>>();
    scan3_kernel<<<NBLK, 256>>>();
    scatter_kernel<<<(ETOT + 255) / 256, 256>>>(src, dst);

    // segmented aggregation, 16 nodes per block
    aggA_kernel<<<(NN + 15) / 16, 256>>>();
    aggB_kernel<<<(NN + 15) / 16, 256>>>(m, out);
}